// round 1
// baseline (speedup 1.0000x reference)
#include <cuda_runtime.h>
#include <cstddef>

// Problem constants
//   x  : (16, 2048, 64, 64) f32
//   W1 : (16, 128, 2048)    f32
//   W2 : (16, 2048, 128)    f32
//   out: (16, 16, 2048, 1, 1) f32
#define B_ 16
#define C_ 2048
#define P_ 16
#define CR_ 128

// Scratch (allocation-free rule: __device__ globals)
__device__ float g_yT[C_ * B_];        // [c][b]   = mean, transposed
__device__ float g_h[P_ * B_ * CR_];   // [p][b][k]

// ---------------------------------------------------------------------------
// Kernel 1: 16x16 patch mean. One warp per (b,c). 2 x LDG.128 per lane.
// ---------------------------------------------------------------------------
__global__ void __launch_bounds__(256) k_mean(const float* __restrict__ x,
                                              float* __restrict__ yT) {
    const int wg   = blockIdx.x * 8 + (threadIdx.x >> 5);  // 0..32767
    const int lane = threadIdx.x & 31;
    const int b = wg >> 11;          // /2048
    const int c = wg & 2047;
    const float* base = x + (size_t)(b * C_ + c) * 4096;   // 64*64 image

    float s = 0.f;
#pragma unroll
    for (int t = 0; t < 2; ++t) {
        const int j    = lane + t * 32;   // float4 index 0..63 within patch
        const int row  = j >> 2;          // 0..15
        const int col4 = j & 3;           // 0..3
        const float4 v = *reinterpret_cast<const float4*>(
            base + (16 + row) * 64 + 16 + col4 * 4);
        s += v.x + v.y + v.z + v.w;
    }
#pragma unroll
    for (int off = 16; off; off >>= 1) s += __shfl_xor_sync(0xffffffffu, s, off);
    if (lane == 0) yT[c * B_ + b] = s * (1.f / 256.f);
}

// ---------------------------------------------------------------------------
// Kernel 2: h[p,b,k] = relu(sum_c W1[p,k,c] * y[b,c])
// Flatten rows m = p*128+k (W1 rows contiguous, length 2048).
// Block: 512 threads = 16 warps, warp per row. y staged in shared, chunked.
// Shared layout ysh[b][cloc] rowstride 516: LDS.128 conflict-free (lane*16B).
// ---------------------------------------------------------------------------
#define YSH_STRIDE 516
#define CHUNK 512

__global__ void __launch_bounds__(512) k_gemm1(const float* __restrict__ W1,
                                               const float* __restrict__ yT,
                                               float* __restrict__ h) {
    __shared__ float ysh[B_ * YSH_STRIDE];
    const int tid  = threadIdx.x;
    const int warp = tid >> 5;
    const int lane = tid & 31;
    const int m    = blockIdx.x * 16 + warp;       // 0..2047
    const float* w1row = W1 + (size_t)m * C_;

    float acc[B_];
#pragma unroll
    for (int b = 0; b < B_; ++b) acc[b] = 0.f;

    for (int ch = 0; ch < C_ / CHUNK; ++ch) {
        const int c0 = ch * CHUNK;
        __syncthreads();
        // cooperative transpose-load: yT[c0+c][b] -> ysh[b][c]
        for (int i = tid; i < CHUNK * B_; i += 512) {
            const int c = i >> 4;
            const int b = i & 15;
            ysh[b * YSH_STRIDE + c] = yT[(c0 + c) * B_ + b];
        }
        __syncthreads();
#pragma unroll
        for (int q = 0; q < CHUNK / 128; ++q) {
            const int cloc = q * 128 + lane * 4;
            const float4 w = *reinterpret_cast<const float4*>(w1row + c0 + cloc);
#pragma unroll
            for (int b = 0; b < B_; ++b) {
                const float4 yv = *reinterpret_cast<const float4*>(
                    &ysh[b * YSH_STRIDE + cloc]);
                acc[b] += w.x * yv.x + w.y * yv.y + w.z * yv.z + w.w * yv.w;
            }
        }
    }

    // cross-lane reduce each of the 16 accumulators; lane b owns b
#pragma unroll
    for (int b = 0; b < B_; ++b) {
        float s = acc[b];
#pragma unroll
        for (int off = 16; off; off >>= 1) s += __shfl_xor_sync(0xffffffffu, s, off);
        if (lane == b) {
            const int p = m >> 7;       // /128
            const int k = m & 127;
            h[(p * B_ + b) * CR_ + k] = fmaxf(s, 0.f);
        }
    }
}

// ---------------------------------------------------------------------------
// Kernel 3: att[p,b,c] = sigmoid(sum_k W2[p,c,k] * h[p,b,k])
// Block: 256 threads = 8 warps, covers (p, 64 c). Warp per c (8 each);
// lane holds W2 k-quad (coalesced LDG.128), h[p] in shared.
// ---------------------------------------------------------------------------
__global__ void __launch_bounds__(256) k_gemm2(const float* __restrict__ W2,
                                               const float* __restrict__ h,
                                               float* __restrict__ out) {
    __shared__ float hsh[B_ * CR_];
    const int tid   = threadIdx.x;
    const int p     = blockIdx.x >> 5;     // 0..15
    const int ctile = blockIdx.x & 31;     // 0..31

    for (int i = tid; i < B_ * CR_; i += 256) hsh[i] = h[p * B_ * CR_ + i];
    __syncthreads();

    const int warp = tid >> 5;
    const int lane = tid & 31;
    const float4* hsh4 = reinterpret_cast<const float4*>(hsh);

#pragma unroll
    for (int i = 0; i < 8; ++i) {
        const int c = ctile * 64 + warp * 8 + i;
        const float4 w = *reinterpret_cast<const float4*>(
            W2 + (size_t)(p * C_ + c) * CR_ + lane * 4);
        float mine = 0.f;
#pragma unroll
        for (int b = 0; b < B_; ++b) {
            const float4 hv = hsh4[b * 32 + lane];
            float s = w.x * hv.x + w.y * hv.y + w.z * hv.z + w.w * hv.w;
#pragma unroll
            for (int off = 16; off; off >>= 1) s += __shfl_xor_sync(0xffffffffu, s, off);
            if (lane == b) mine = s;
        }
        if (lane < 16) {
            const float sig = 1.f / (1.f + __expf(-mine));
            out[(size_t)(p * B_ + lane) * C_ + c] = sig;  // lane = b
        }
    }
}

// ---------------------------------------------------------------------------
extern "C" void kernel_launch(void* const* d_in, const int* in_sizes, int n_in,
                              void* d_out, int out_size) {
    const float* x  = (const float*)d_in[0];
    const float* W1 = (const float*)d_in[1];
    const float* W2 = (const float*)d_in[2];
    float* out      = (float*)d_out;

    float* yT;
    float* h;
    cudaGetSymbolAddress((void**)&yT, g_yT);
    cudaGetSymbolAddress((void**)&h, g_h);

    k_mean <<<(B_ * C_) / 8, 256>>>(x, yT);
    k_gemm1<<<(P_ * CR_) / 16, 512>>>(W1, yT, h);
    k_gemm2<<<P_ * 32, 256>>>(W2, h, out);
}

// round 2
// speedup vs baseline: 1.3727x; 1.3727x over previous
#include <cuda_runtime.h>
#include <cstddef>

// Problem constants
//   x  : (16, 2048, 64, 64) f32
//   W1 : (16, 128, 2048)    f32
//   W2 : (16, 2048, 128)    f32
//   out: (16, 16, 2048) f32
#define B_ 16
#define C_ 2048
#define P_ 16
#define CR_ 128

// Scratch (__device__ globals: allocation-free rule)
__device__ float g_yT[C_ * B_];               // [c][b] patch means
__device__ float g_hp[2 * P_ * B_ * CR_];     // split-K partial h, [half][p][b][k]

// ---------------------------------------------------------------------------
// Kernel 1: 16x16 patch mean. Thread per patch-row: 4 consecutive LDG.128
// (MLP_p1 = 4). Half-warp (16-lane) butterfly reduce.
// ---------------------------------------------------------------------------
__global__ void __launch_bounds__(256) k_mean(const float* __restrict__ x,
                                              float* __restrict__ yT) {
    const int t     = blockIdx.x * 256 + threadIdx.x;   // 0 .. 524287
    const int patch = t >> 4;                           // (b,c) flattened
    const int row   = t & 15;
    const float4* src = reinterpret_cast<const float4*>(
        x + (size_t)patch * 4096 + (16 + row) * 64 + 16);

    const float4 v0 = src[0];
    const float4 v1 = src[1];
    const float4 v2 = src[2];
    const float4 v3 = src[3];
    float s = (v0.x + v0.y + v0.z + v0.w) + (v1.x + v1.y + v1.z + v1.w)
            + (v2.x + v2.y + v2.z + v2.w) + (v3.x + v3.y + v3.z + v3.w);

#pragma unroll
    for (int off = 8; off; off >>= 1) s += __shfl_xor_sync(0xffffffffu, s, off);

    if (row == 0) {
        const int b = patch >> 11;
        const int c = patch & 2047;
        yT[c * B_ + b] = s * (1.f / 256.f);
    }
}

// ---------------------------------------------------------------------------
// Kernel 2: partial h[p,b,k] = sum_{c in half} W1[p,k,c] * y[b,c]
// Rows m = p*128+k. Warp owns 4 rows (register blocking cuts LDS 4x).
// Split-K = 2 halves of c so grid = 128 blocks fills the chip.
// relu deferred to kernel 3 (applied after halves are summed).
// ---------------------------------------------------------------------------
#define YSH_STRIDE 516
#define CHUNK 512

__global__ void __launch_bounds__(256) k_gemm1(const float* __restrict__ W1,
                                               const float* __restrict__ yT,
                                               float* __restrict__ hp) {
    __shared__ float ysh[B_ * YSH_STRIDE];   // 33 KB
    const int tid   = threadIdx.x;
    const int warp  = tid >> 5;
    const int lane  = tid & 31;
    const int mtile = blockIdx.x >> 1;       // 0..63 (32 rows each)
    const int half  = blockIdx.x & 1;        // c-half
    const int m0    = mtile * 32 + warp * 4;
    const int cbase0 = half * 1024;
    const float* w0 = W1 + (size_t)m0 * C_ + cbase0;

    float acc[4][16];
#pragma unroll
    for (int r = 0; r < 4; ++r)
#pragma unroll
        for (int b = 0; b < B_; ++b) acc[r][b] = 0.f;

#pragma unroll
    for (int ch = 0; ch < 2; ++ch) {
        const int cbase = ch * CHUNK;
        __syncthreads();
        // stage y chunk: ysh[b][c] <- yT[cbase0+cbase+c][b]; fully coalesced read
        for (int i = tid; i < CHUNK * B_; i += 256) {
            const int c = i >> 4;
            const int b = i & 15;
            ysh[b * YSH_STRIDE + c] = yT[(cbase0 + cbase + c) * B_ + b];
        }
        __syncthreads();
#pragma unroll
        for (int q = 0; q < CHUNK / 128; ++q) {
            const int cloc = q * 128 + lane * 4;
            float4 w[4];
#pragma unroll
            for (int r = 0; r < 4; ++r)
                w[r] = *reinterpret_cast<const float4*>(w0 + (size_t)r * C_ + cbase + cloc);
#pragma unroll
            for (int b = 0; b < B_; ++b) {
                const float4 yv = *reinterpret_cast<const float4*>(&ysh[b * YSH_STRIDE + cloc]);
#pragma unroll
                for (int r = 0; r < 4; ++r)
                    acc[r][b] += w[r].x * yv.x + w[r].y * yv.y + w[r].z * yv.z + w[r].w * yv.w;
            }
        }
    }

    // cross-lane reduce; lane b stores row r's (b) partial
#pragma unroll
    for (int r = 0; r < 4; ++r) {
#pragma unroll
        for (int b = 0; b < B_; ++b) {
            float s = acc[r][b];
#pragma unroll
            for (int off = 16; off; off >>= 1) s += __shfl_xor_sync(0xffffffffu, s, off);
            if (lane == b) {
                const int m = m0 + r;
                const int p = m >> 7;
                const int k = m & 127;
                hp[half * (P_ * B_ * CR_) + (p * B_ + b) * CR_ + k] = s;
            }
        }
    }
}

// ---------------------------------------------------------------------------
// Kernel 3: att[p,b,c] = sigmoid(sum_k W2[p,c,k] * relu(h[p,b,k]))
// Thread per (p,c): 16 b-accumulators in registers, h[p] in shared read as
// warp-uniform broadcast (zero shuffles). Packed f32x2 FMA over k-pairs.
// ---------------------------------------------------------------------------
__device__ __forceinline__ void fma2(unsigned long long& d,
                                     unsigned long long a,
                                     unsigned long long b) {
    asm("fma.rn.f32x2 %0, %1, %2, %0;" : "+l"(d) : "l"(a), "l"(b));
}

__global__ void __launch_bounds__(128) k_gemm2(const float* __restrict__ W2,
                                               const float* __restrict__ hp,
                                               float* __restrict__ out) {
    __shared__ float hsh[B_ * CR_];          // 8 KB
    const int tid   = threadIdx.x;
    const int p     = blockIdx.x >> 4;
    const int ctile = blockIdx.x & 15;

    // combine split-K partials + relu
    for (int i = tid; i < B_ * CR_; i += 128) {
        const float v = hp[p * (B_ * CR_) + i] + hp[P_ * B_ * CR_ + p * (B_ * CR_) + i];
        hsh[i] = fmaxf(v, 0.f);
    }
    __syncthreads();

    const int c = ctile * 128 + tid;
    const ulonglong2* w2 = reinterpret_cast<const ulonglong2*>(
        W2 + (size_t)(p * C_ + c) * CR_);
    const ulonglong2* h2 = reinterpret_cast<const ulonglong2*>(hsh);

    unsigned long long acc[16];
#pragma unroll
    for (int b = 0; b < B_; ++b) acc[b] = 0ull;   // (0.f, 0.f)

#pragma unroll 4
    for (int kq = 0; kq < 32; ++kq) {
        const ulonglong2 w = w2[kq];
#pragma unroll
        for (int b = 0; b < B_; ++b) {
            const ulonglong2 hv = h2[b * 32 + kq];   // warp-uniform -> broadcast
            fma2(acc[b], w.x, hv.x);
            fma2(acc[b], w.y, hv.y);
        }
    }

#pragma unroll
    for (int b = 0; b < B_; ++b) {
        float lo, hi;
        asm("mov.b64 {%0, %1}, %2;" : "=f"(lo), "=f"(hi) : "l"(acc[b]));
        const float s = lo + hi;
        out[(size_t)(p * B_ + b) * C_ + c] = 1.f / (1.f + __expf(-s));
    }
}

// ---------------------------------------------------------------------------
extern "C" void kernel_launch(void* const* d_in, const int* in_sizes, int n_in,
                              void* d_out, int out_size) {
    const float* x  = (const float*)d_in[0];
    const float* W1 = (const float*)d_in[1];
    const float* W2 = (const float*)d_in[2];
    float* out      = (float*)d_out;

    float* yT;
    float* hp;
    cudaGetSymbolAddress((void**)&yT, g_yT);
    cudaGetSymbolAddress((void**)&hp, g_hp);

    k_mean <<<(B_ * C_ * 16) / 256, 256>>>(x, yT);
    k_gemm1<<<128, 256>>>(W1, yT, hp);
    k_gemm2<<<P_ * 16, 128>>>(W2, hp, out);
}

// round 3
// speedup vs baseline: 1.7148x; 1.2492x over previous
#include <cuda_runtime.h>
#include <cstddef>

// Problem constants
//   x  : (16, 2048, 64, 64) f32
//   W1 : (16, 128, 2048)    f32
//   W2 : (16, 2048, 128)    f32
//   out: (16, 16, 2048) f32
#define B_ 16
#define C_ 2048
#define P_ 16
#define CR_ 128

// Scratch (__device__ globals: allocation-free rule)
__device__ float g_yT[C_ * B_];               // [c][b] patch means
__device__ float g_hp[2 * P_ * B_ * CR_];     // split-K partial h, [half][p][b][k]

// f32x2 packed helpers -------------------------------------------------------
__device__ __forceinline__ void fma2(unsigned long long& d,
                                     unsigned long long a,
                                     unsigned long long b) {
    asm("fma.rn.f32x2 %0, %1, %2, %0;" : "+l"(d) : "l"(a), "l"(b));
}
__device__ __forceinline__ void add2(unsigned long long& d, unsigned long long v) {
    asm("add.rn.f32x2 %0, %0, %1;" : "+l"(d) : "l"(v));
}
__device__ __forceinline__ unsigned long long dup2(float w) {
    unsigned long long r;
    asm("mov.b64 %0, {%1, %1};" : "=l"(r) : "f"(w));
    return r;
}
__device__ __forceinline__ float2 unpack2(unsigned long long v) {
    float lo, hi;
    asm("mov.b64 {%0, %1}, %2;" : "=f"(lo), "=f"(hi) : "l"(v));
    return make_float2(lo, hi);
}

// ---------------------------------------------------------------------------
// Kernel 1: 16x16 patch mean. Warp handles 2 patches (half-warp each).
// 4 independent LDG.128 per thread; each warp-LDG touches only 8 cache lines.
// ---------------------------------------------------------------------------
__global__ void __launch_bounds__(256) k_mean(const float* __restrict__ x,
                                              float* __restrict__ yT) {
    const int warp  = blockIdx.x * 8 + (threadIdx.x >> 5);   // 0..16383
    const int lane  = threadIdx.x & 31;
    const int hw    = lane >> 4;
    const int hl    = lane & 15;
    const int patch = warp * 2 + hw;                          // 0..32767
    const float* base = x + (size_t)patch * 4096 + 16 * 64 + 16;

    float s = 0.f;
#pragma unroll
    for (int t = 0; t < 4; ++t) {
        const int j    = hl + t * 16;   // float4 index 0..63
        const int row  = j >> 2;
        const int col4 = j & 3;
        const float4 v = __ldcs(reinterpret_cast<const float4*>(
            base + row * 64 + col4 * 4));
        s += (v.x + v.y) + (v.z + v.w);
    }
#pragma unroll
    for (int off = 8; off; off >>= 1) s += __shfl_xor_sync(0xffffffffu, s, off);

    if (hl == 0) {
        const int b = patch >> 11;
        const int c = patch & 2047;
        yT[c * B_ + b] = s * (1.f / 256.f);
    }
}

// ---------------------------------------------------------------------------
// Kernel 2: partial h[p,b,k] = sum_{c in half} W1[p,k,c] * y[b,c]
// Warp owns 4 rows m. y staged b-major as float4: ysh4[bq][c] = y[4bq..4bq+3][c].
// Per q-iter each lane owns 1 c: LDS.128 conflict-free (bank = 8bq+4lane).
// Accumulation in packed f32x2.
// ---------------------------------------------------------------------------
#define YSTRIDE 514   // float4 row stride (pad): 2056 words = 8 mod 32

__global__ void __launch_bounds__(256) k_gemm1(const float* __restrict__ W1,
                                               const float* __restrict__ yT,
                                               float* __restrict__ hp) {
    __shared__ float4 ysh4[4 * YSTRIDE];     // 32.9 KB, one 512-c chunk
    const int tid   = threadIdx.x;
    const int warp  = tid >> 5;
    const int lane  = tid & 31;
    const int mtile = blockIdx.x >> 1;       // 0..63
    const int half  = blockIdx.x & 1;        // c-half (split-K)
    const int m0    = mtile * 32 + warp * 4;
    const int cbase0 = half * 1024;
    const float* w1base = W1 + (size_t)m0 * C_ + cbase0;

    unsigned long long acc[4][4][2];         // [r][bq][pair] : (b even, b odd)
#pragma unroll
    for (int r = 0; r < 4; ++r)
#pragma unroll
        for (int bq = 0; bq < 4; ++bq) { acc[r][bq][0] = 0ull; acc[r][bq][1] = 0ull; }

#pragma unroll
    for (int ch = 0; ch < 2; ++ch) {
        const int cb = ch * 512;
        __syncthreads();
        // stage: ysh4[bq][c] <- (float4)&yT[(c)*16 + bq*4]; fully coalesced.
        for (int i = tid; i < 512 * 4; i += 256) {
            const int c  = i >> 2;
            const int bq = i & 3;
            ysh4[bq * YSTRIDE + c] =
                *reinterpret_cast<const float4*>(&yT[(cbase0 + cb + c) * B_ + bq * 4]);
        }
        __syncthreads();

#pragma unroll 4
        for (int q = 0; q < 16; ++q) {
            const int c = q * 32 + lane;
            // 4 scalar W1 loads, coalesced (lanes = consecutive c)
            unsigned long long wd[4];
#pragma unroll
            for (int r = 0; r < 4; ++r)
                wd[r] = dup2(w1base[(size_t)r * C_ + cb + c]);
#pragma unroll
            for (int bq = 0; bq < 4; ++bq) {
                const ulonglong2 yv = *reinterpret_cast<const ulonglong2*>(
                    &ysh4[bq * YSTRIDE + c]);
#pragma unroll
                for (int r = 0; r < 4; ++r) {
                    fma2(acc[r][bq][0], wd[r], yv.x);
                    fma2(acc[r][bq][1], wd[r], yv.y);
                }
            }
        }
    }

    // cross-lane butterfly on packed accumulators
#pragma unroll
    for (int r = 0; r < 4; ++r)
#pragma unroll
        for (int bq = 0; bq < 4; ++bq)
#pragma unroll
            for (int e = 0; e < 2; ++e)
#pragma unroll
                for (int off = 16; off; off >>= 1)
                    add2(acc[r][bq][e],
                         __shfl_xor_sync(0xffffffffu, acc[r][bq][e], off));

    if (lane < 16) {
        const int b  = lane;
        const int bq = b >> 2;
        const int e  = (b >> 1) & 1;
        const int hi = b & 1;
        float4 hv;
        {
            const float2 v0 = unpack2(acc[0][bq][e]);
            const float2 v1 = unpack2(acc[1][bq][e]);
            const float2 v2 = unpack2(acc[2][bq][e]);
            const float2 v3 = unpack2(acc[3][bq][e]);
            hv.x = hi ? v0.y : v0.x;
            hv.y = hi ? v1.y : v1.x;
            hv.z = hi ? v2.y : v2.x;
            hv.w = hi ? v3.y : v3.x;
        }
        const int p  = m0 >> 7;
        const int k0 = m0 & 127;
        *reinterpret_cast<float4*>(
            &hp[half * (P_ * B_ * CR_) + (p * B_ + b) * CR_ + k0]) = hv;
    }
}

// ---------------------------------------------------------------------------
// Kernel 3: att[p,b,c] = sigmoid(sum_k W2[p,c,k] * relu(h[p,b,k]))
// W2 tile (128 c x 128 k = 64 KB) staged in shared with pad-132 rows
// (coalesced LDG, conflict-free LDS.128). Thread per c, f32x2 accumulation,
// h[p] broadcast from shared.
// ---------------------------------------------------------------------------
#define W2STRIDE 132
#define G2_SMEM ((128 * W2STRIDE + B_ * CR_) * 4)   // 75776 bytes

__global__ void __launch_bounds__(128) k_gemm2(const float* __restrict__ W2,
                                               const float* __restrict__ hp,
                                               float* __restrict__ out) {
    extern __shared__ float smem[];
    float* w2sh = smem;                       // [128][132]
    float* hsh  = smem + 128 * W2STRIDE;      // [16][128]

    const int tid   = threadIdx.x;
    const int p     = blockIdx.x >> 4;
    const int ctile = blockIdx.x & 15;

    // combine split-K partials + relu
    for (int i = tid; i < B_ * CR_; i += 128) {
        const float v = hp[p * (B_ * CR_) + i]
                      + hp[P_ * B_ * CR_ + p * (B_ * CR_) + i];
        hsh[i] = fmaxf(v, 0.f);
    }
    // stage W2 tile, coalesced float4 loads
    const float4* wsrc = reinterpret_cast<const float4*>(
        W2 + (size_t)(p * C_ + ctile * 128) * CR_);
    for (int i = tid; i < 128 * 32; i += 128) {
        const int row  = i >> 5;
        const int quad = i & 31;
        *reinterpret_cast<float4*>(&w2sh[row * W2STRIDE + quad * 4]) = wsrc[i];
    }
    __syncthreads();

    const ulonglong2* wrow = reinterpret_cast<const ulonglong2*>(&w2sh[tid * W2STRIDE]);
    const ulonglong2* h2   = reinterpret_cast<const ulonglong2*>(hsh);

    unsigned long long acc[16];
#pragma unroll
    for (int b = 0; b < B_; ++b) acc[b] = 0ull;

#pragma unroll 4
    for (int kq = 0; kq < 32; ++kq) {
        const ulonglong2 w = wrow[kq];
#pragma unroll
        for (int b = 0; b < B_; ++b) {
            const ulonglong2 hv = h2[b * 32 + kq];   // warp-uniform broadcast
            fma2(acc[b], w.x, hv.x);
            fma2(acc[b], w.y, hv.y);
        }
    }

    const int c = ctile * 128 + tid;
#pragma unroll
    for (int b = 0; b < B_; ++b) {
        const float2 v = unpack2(acc[b]);
        const float s = v.x + v.y;
        out[(size_t)(p * B_ + b) * C_ + c] = 1.f / (1.f + __expf(-s));
    }
}

// ---------------------------------------------------------------------------
extern "C" void kernel_launch(void* const* d_in, const int* in_sizes, int n_in,
                              void* d_out, int out_size) {
    const float* x  = (const float*)d_in[0];
    const float* W1 = (const float*)d_in[1];
    const float* W2 = (const float*)d_in[2];
    float* out      = (float*)d_out;

    float* yT;
    float* hp;
    cudaGetSymbolAddress((void**)&yT, g_yT);
    cudaGetSymbolAddress((void**)&hp, g_hp);

    cudaFuncSetAttribute(k_gemm2, cudaFuncAttributeMaxDynamicSharedMemorySize,
                         G2_SMEM);

    k_mean <<<2048, 256>>>(x, yT);
    k_gemm1<<<128, 256>>>(W1, yT, hp);
    k_gemm2<<<256, 128, G2_SMEM>>>(W2, hp, out);
}